// round 5
// baseline (speedup 1.0000x reference)
#include <cuda_runtime.h>
#include <cuda_fp16.h>
#include <math.h>
#include <stdint.h>

#define D_MODEL 1024
#define D_FF    4096
#define NE      8
#define NT      8192
#define ROWS_MAX 17408
#define NTILES  136             // ROWS_MAX/128 m-tiles

// ---------------- static scratch (no runtime allocation allowed) ----------------
__device__ int    g_topk_idx[NT * 2];
__device__ float  g_topk_prob[NT * 2];
__device__ int    g_pos[NT * 2];
__device__ int    g_counts[NE];
__device__ float  g_probs_sum[NE];
__device__ int    g_poff[NE + 1];
__device__ int    g_cursor[NE];
__device__ __half g_xa[(size_t)ROWS_MAX * D_MODEL];       // permuted fp16 A for GEMM1
__device__ __half g_w1t[(size_t)NE * D_FF * D_MODEL];     // w1^T [e][f][k] fp16
__device__ __half g_w2t[(size_t)NE * D_MODEL * D_FF];     // w2^T [e][d][k] fp16
__device__ __half g_h[(size_t)ROWS_MAX * D_FF];           // GEMM1 out fp16
__device__ float  g_y[(size_t)ROWS_MAX * D_MODEL];        // GEMM2 out fp32

// ---------------- PTX helpers (arch-portable only!) ----------------
__device__ __forceinline__ uint32_t smem_to_u32(const void* p) {
    uint32_t a;
    asm("{ .reg .u64 t; cvta.to.shared.u64 t, %1; cvt.u32.u64 %0, t; }" : "=r"(a) : "l"(p));
    return a;
}
__device__ __forceinline__ void cp16(uint32_t s, const void* g) {
    asm volatile("cp.async.cg.shared.global [%0], [%1], 16;\n" :: "r"(s), "l"(g) : "memory");
}
#define CP_COMMIT() asm volatile("cp.async.commit_group;\n" ::: "memory")
#define CP_WAIT(n)  asm volatile("cp.async.wait_group %0;\n" :: "n"(n) : "memory")

__device__ __forceinline__ void ldsm_x4(uint32_t& r0, uint32_t& r1, uint32_t& r2,
                                        uint32_t& r3, uint32_t addr) {
    asm volatile("ldmatrix.sync.aligned.m8n8.x4.shared.b16 {%0,%1,%2,%3}, [%4];"
                 : "=r"(r0), "=r"(r1), "=r"(r2), "=r"(r3) : "r"(addr));
}
__device__ __forceinline__ void mma_f16(float* c, const uint32_t* a, const uint32_t* b) {
    asm volatile(
        "mma.sync.aligned.m16n8k16.row.col.f32.f16.f16.f32 "
        "{%0,%1,%2,%3},{%4,%5,%6,%7},{%8,%9},{%0,%1,%2,%3};"
        : "+f"(c[0]), "+f"(c[1]), "+f"(c[2]), "+f"(c[3])
        : "r"(a[0]), "r"(a[1]), "r"(a[2]), "r"(a[3]), "r"(b[0]), "r"(b[1]));
}

// ---------------- init ----------------
__global__ void k_init() {
    int i = threadIdx.x;
    if (i < NE) { g_counts[i] = 0; g_probs_sum[i] = 0.f; g_cursor[i] = 0; }
}

// ---------------- router: 1 warp per token ----------------
__global__ void __launch_bounds__(256) k_router(const float* __restrict__ x,
                                                const float* __restrict__ gw,
                                                const float* __restrict__ gb) {
    __shared__ float gws[NE * D_MODEL];
    __shared__ float psum[NE];
    __shared__ int   scnt[NE];
    int tid = threadIdx.x;
    for (int i = tid; i < NE * D_MODEL; i += 256) {
        int d = i >> 3, e = i & 7;
        gws[e * D_MODEL + d] = gw[i];
    }
    if (tid < NE) { psum[tid] = 0.f; scnt[tid] = 0; }
    __syncthreads();

    int lane = tid & 31, warp = tid >> 5;
    int t = blockIdx.x * 8 + warp;
    const float* xr = x + (size_t)t * D_MODEL;

    float acc[NE];
#pragma unroll
    for (int e = 0; e < NE; e++) acc[e] = 0.f;
    for (int i = 0; i < D_MODEL / 32; i++) {
        int d = i * 32 + lane;
        float xv = xr[d];
#pragma unroll
        for (int e = 0; e < NE; e++) acc[e] += xv * gws[e * D_MODEL + d];
    }
#pragma unroll
    for (int e = 0; e < NE; e++)
        for (int off = 16; off > 0; off >>= 1)
            acc[e] += __shfl_xor_sync(0xffffffffu, acc[e], off);

    if (lane == 0) {
        float l[NE], p[NE];
        float m = -1e30f;
#pragma unroll
        for (int e = 0; e < NE; e++) { l[e] = acc[e] + gb[e]; m = fmaxf(m, l[e]); }
        float s = 0.f;
#pragma unroll
        for (int e = 0; e < NE; e++) { p[e] = expf(l[e] - m); s += p[e]; }
        float inv = 1.f / s;
#pragma unroll
        for (int e = 0; e < NE; e++) { p[e] *= inv; atomicAdd(&psum[e], p[e]); }
        int e1 = 0;
#pragma unroll
        for (int e = 1; e < NE; e++) if (p[e] > p[e1]) e1 = e;
        int e2 = -1;
#pragma unroll
        for (int e = 0; e < NE; e++) {
            if (e == e1) continue;
            if (e2 < 0 || p[e] > p[e2]) e2 = e;
        }
        float pr = 1.f / (p[e1] + p[e2]);
        g_topk_idx[2 * t] = e1;     g_topk_idx[2 * t + 1] = e2;
        g_topk_prob[2 * t] = p[e1] * pr; g_topk_prob[2 * t + 1] = p[e2] * pr;
        atomicAdd(&scnt[e1], 1);
        atomicAdd(&scnt[e2], 1);
    }
    __syncthreads();
    if (tid < NE) {
        atomicAdd(&g_probs_sum[tid], psum[tid]);
        atomicAdd(&g_counts[tid], scnt[tid]);
    }
}

// ---------------- stats + padded segment offsets ----------------
__global__ void k_stats(float* __restrict__ out) {
    if (threadIdx.x == 0) {
        int off = 0;
        for (int e = 0; e < NE; e++) {
            g_poff[e] = off;
            off += ((g_counts[e] + 127) >> 7) << 7;
        }
        g_poff[NE] = off;
        float* tail = out + (size_t)NT * D_MODEL;
        for (int e = 0; e < NE; e++) tail[e] = (float)g_counts[e] / (float)(NT * 2);
        float avg[NE], mean = 0.f;
        for (int e = 0; e < NE; e++) { avg[e] = g_probs_sum[e] / (float)NT; mean += avg[e]; }
        mean /= (float)NE;
        float var = 0.f;
        for (int e = 0; e < NE; e++) { float d = avg[e] - mean; var += d * d; }
        tail[NE] = var / (float)(NE - 1);   // ddof=1
    }
}

// ---------------- scatter slots ----------------
__global__ void k_scatter() {
    int s = blockIdx.x * blockDim.x + threadIdx.x;
    int e = g_topk_idx[s];
    int p = g_poff[e] + atomicAdd(&g_cursor[e], 1);
    g_pos[s] = p;
}

// ---------------- pack: x rows -> permuted fp16 A ----------------
__global__ void __launch_bounds__(256) k_pack(const float* __restrict__ x) {
    int s = blockIdx.x;
    int tok = s >> 1;
    int p = g_pos[s];
    int i = threadIdx.x;
    float4 v = *(const float4*)&x[(size_t)tok * D_MODEL + i * 4];
    __half2 h0 = __floats2half2_rn(v.x, v.y);
    __half2 h1 = __floats2half2_rn(v.z, v.w);
    __half2* dst = (__half2*)&g_xa[(size_t)p * D_MODEL + i * 4];
    dst[0] = h0;
    dst[1] = h1;
}

// ---------------- weight transpose to K-major fp16 ----------------
// src fp32 [e][R][C] -> dst fp16 [e][C][R]
template <int R, int C>
__global__ void __launch_bounds__(256) k_transpose(const float* __restrict__ src,
                                                   __half* __restrict__ dst) {
    __shared__ float t[32][33];
    int e = blockIdx.z;
    const float* s = src + (size_t)e * R * C;
    __half* d = dst + (size_t)e * R * C;
    int c0 = blockIdx.x * 32, r0 = blockIdx.y * 32;
#pragma unroll
    for (int j = 0; j < 32; j += 8)
        t[threadIdx.y + j][threadIdx.x] =
            s[(size_t)(r0 + threadIdx.y + j) * C + c0 + threadIdx.x];
    __syncthreads();
#pragma unroll
    for (int j = 0; j < 32; j += 8)
        d[(size_t)(c0 + threadIdx.y + j) * R + r0 + threadIdx.x] =
            __float2half_rn(t[threadIdx.x][threadIdx.y + j]);
}

// ---------------- fp16 mma GEMM: block 128m x 256n, K-chunk 64, 3-stage cp.async ----
// SMEM per stage: A 128 rows * 128B = 16KB; B 256 rows * 128B = 32KB
#define ST_A 16384
#define ST_B 32768
#define SMEM_GEMM (3 * (ST_A + ST_B))   // 147456

__device__ __forceinline__ void fill_stage(uint32_t aS, uint32_t bS,
                                           const __half* __restrict__ Ab,
                                           const __half* __restrict__ Bb,
                                           int koff, int kdim, int tid) {
#pragma unroll
    for (int i = 0; i < 4; i++) {           // A: 128 rows * 8 chunks = 1024 cp16
        int id = tid + i * 256;
        int row = id >> 3, ch = id & 7;
        uint32_t dst = aS + row * 128 + ((uint32_t)(ch ^ (row & 7)) << 4);
        cp16(dst, Ab + (size_t)row * kdim + koff + ch * 8);
    }
#pragma unroll
    for (int i = 0; i < 8; i++) {           // B: 256 rows * 8 chunks = 2048 cp16
        int id = tid + i * 256;
        int row = id >> 3, ch = id & 7;
        uint32_t dst = bS + row * 128 + ((uint32_t)(ch ^ (row & 7)) << 4);
        cp16(dst, Bb + (size_t)row * kdim + koff + ch * 8);
    }
}

template <int KDIM, int NDIM, bool FIRST>
__global__ void __launch_bounds__(256, 1) k_gemm_f16(const __half* __restrict__ Bg,
                                                     const float* __restrict__ bias) {
    extern __shared__ char smem[];
    const int row0 = blockIdx.x * 128;
    if (row0 >= g_poff[NE]) return;
    int e = 0;
#pragma unroll
    for (int i = 1; i < NE; i++) if (row0 >= g_poff[i]) e = i;
    const int n0 = blockIdx.y * 256;
    const int tid = threadIdx.x, lane = tid & 31, wid = tid >> 5;
    const int wm = wid & 1, wn = wid >> 1;          // 2 x 4 warp grid, 64x64 per warp
    const uint32_t sA = smem_to_u32(smem);
    const uint32_t sB = sA + 3 * ST_A;
    const __half* Ab = (FIRST ? g_xa : g_h) + (size_t)row0 * KDIM;
    const __half* Bb = Bg + (size_t)e * KDIM * NDIM + (size_t)n0 * KDIM;
    const int NKT = KDIM / 64;

    // prologue: 2 stages in flight
    fill_stage(sA, sB, Ab, Bb, 0, KDIM, tid);
    CP_COMMIT();
    fill_stage(sA + ST_A, sB + ST_B, Ab, Bb, 64, KDIM, tid);
    CP_COMMIT();

    float acc[4][8][4];
#pragma unroll
    for (int a = 0; a < 4; a++)
#pragma unroll
        for (int b = 0; b < 8; b++)
#pragma unroll
            for (int c = 0; c < 4; c++) acc[a][b][c] = 0.f;

    const int m0w = wm * 64, n0w = wn * 64;
    const int lrA = lane & 15;                  // A row within frag
    const int lqA = lane >> 4;                  // A k-half select
    const int lrB = (lane & 7) + ((lane & 16) >> 1);   // B row within n16 group
    const int lkB = (lane >> 3) & 1;            // B k-half select
    const int lsw = lane & 7;                   // swizzle row bits

#pragma unroll 1
    for (int kt = 0; kt < NKT; kt++) {
        CP_WAIT(1);
        __syncthreads();
        const int cn = kt + 2;
        if (cn < NKT) {
            const int s2 = cn % 3;
            fill_stage(sA + s2 * ST_A, sB + s2 * ST_B, Ab, Bb, cn * 64, KDIM, tid);
        }
        CP_COMMIT();
        const int s = kt % 3;
        const uint32_t aS = sA + s * ST_A, bS = sB + s * ST_B;
#pragma unroll
        for (int kk = 0; kk < 4; kk++) {
            const uint32_t swA = (uint32_t)(((kk * 2 + lqA) ^ lsw) << 4);
            const uint32_t swB = (uint32_t)(((kk * 2 + lkB) ^ lsw) << 4);
            uint32_t a[4][4];
#pragma unroll
            for (int mf = 0; mf < 4; mf++) {
                uint32_t addr = aS + (uint32_t)(m0w + mf * 16 + lrA) * 128 + swA;
                ldsm_x4(a[mf][0], a[mf][1], a[mf][2], a[mf][3], addr);
            }
#pragma unroll
            for (int nf = 0; nf < 4; nf++) {
                uint32_t b[4];
                uint32_t addr = bS + (uint32_t)(n0w + nf * 16 + lrB) * 128 + swB;
                ldsm_x4(b[0], b[1], b[2], b[3], addr);
#pragma unroll
                for (int mf = 0; mf < 4; mf++) {
                    mma_f16(acc[mf][nf * 2],     a[mf], b);
                    mma_f16(acc[mf][nf * 2 + 1], a[mf], b + 2);
                }
            }
        }
    }

    // epilogue
    const int gid = lane >> 2, ktid = lane & 3;
#pragma unroll
    for (int mf = 0; mf < 4; mf++) {
        const int r0 = row0 + m0w + mf * 16 + gid;
        const int r1 = r0 + 8;
#pragma unroll
        for (int nf8 = 0; nf8 < 8; nf8++) {
            const int col = n0 + n0w + nf8 * 8 + ktid * 2;
            float* c = acc[mf][nf8];
            if (FIRST) {
                float b0v = bias[e * NDIM + col];
                float b1v = bias[e * NDIM + col + 1];
                __half2 h0 = __floats2half2_rn(fmaxf(c[0] + b0v, 0.f), fmaxf(c[1] + b1v, 0.f));
                __half2 h1 = __floats2half2_rn(fmaxf(c[2] + b0v, 0.f), fmaxf(c[3] + b1v, 0.f));
                *(__half2*)&g_h[(size_t)r0 * NDIM + col] = h0;
                *(__half2*)&g_h[(size_t)r1 * NDIM + col] = h1;
            } else {
                *(float2*)&g_y[(size_t)r0 * NDIM + col] = make_float2(c[0], c[1]);
                *(float2*)&g_y[(size_t)r1 * NDIM + col] = make_float2(c[2], c[3]);
            }
        }
    }
}

// ---------------- combine ----------------
__global__ void __launch_bounds__(256) k_combine(const float* __restrict__ b2,
                                                 float* __restrict__ out) {
    int t = blockIdx.x, i = threadIdx.x;
    int e0 = g_topk_idx[2 * t], e1 = g_topk_idx[2 * t + 1];
    float p0 = g_topk_prob[2 * t], p1 = g_topk_prob[2 * t + 1];
    int q0 = g_pos[2 * t], q1 = g_pos[2 * t + 1];
    float4 y0 = *(const float4*)&g_y[(size_t)q0 * D_MODEL + i * 4];
    float4 y1 = *(const float4*)&g_y[(size_t)q1 * D_MODEL + i * 4];
    float4 c0 = *(const float4*)&b2[(size_t)e0 * D_MODEL + i * 4];
    float4 c1 = *(const float4*)&b2[(size_t)e1 * D_MODEL + i * 4];
    float4 o;
    o.x = p0 * (y0.x + c0.x) + p1 * (y1.x + c1.x);
    o.y = p0 * (y0.y + c0.y) + p1 * (y1.y + c1.y);
    o.z = p0 * (y0.z + c0.z) + p1 * (y1.z + c1.z);
    o.w = p0 * (y0.w + c0.w) + p1 * (y1.w + c1.w);
    *(float4*)&out[(size_t)t * D_MODEL + i * 4] = o;
}

// ---------------- launch ----------------
extern "C" void kernel_launch(void* const* d_in, const int* in_sizes, int n_in,
                              void* d_out, int out_size) {
    (void)in_sizes; (void)n_in; (void)out_size;
    const float* x  = (const float*)d_in[0];
    const float* gw = (const float*)d_in[1];
    const float* gb = (const float*)d_in[2];
    const float* w1 = (const float*)d_in[3];
    const float* b1 = (const float*)d_in[4];
    const float* w2 = (const float*)d_in[5];
    const float* b2 = (const float*)d_in[6];
    float* out = (float*)d_out;

    static int attr_done = 0;
    if (!attr_done) {
        cudaFuncSetAttribute(k_gemm_f16<D_MODEL, D_FF, true>,
                             cudaFuncAttributeMaxDynamicSharedMemorySize, SMEM_GEMM);
        cudaFuncSetAttribute(k_gemm_f16<D_FF, D_MODEL, false>,
                             cudaFuncAttributeMaxDynamicSharedMemorySize, SMEM_GEMM);
        attr_done = 1;
    }

    k_init<<<1, 32>>>();
    k_router<<<NT / 8, 256>>>(x, gw, gb);
    k_stats<<<1, 32>>>(out);
    k_scatter<<<(NT * 2) / 256, 256>>>();
    k_pack<<<NT * 2, 256>>>(x);
    k_transpose<D_MODEL, D_FF><<<dim3(D_FF / 32, D_MODEL / 32, NE), dim3(32, 8)>>>(w1, g_w1t);
    k_transpose<D_FF, D_MODEL><<<dim3(D_MODEL / 32, D_FF / 32, NE), dim3(32, 8)>>>(w2, g_w2t);
    k_gemm_f16<D_MODEL, D_FF, true ><<<dim3(NTILES, D_FF / 256), 256, SMEM_GEMM>>>(g_w1t, b1);
    k_gemm_f16<D_FF, D_MODEL, false><<<dim3(NTILES, D_MODEL / 256), 256, SMEM_GEMM>>>(g_w2t, (const float*)0);
    k_combine<<<NT, 256>>>(b2, out);
}

// round 6
// speedup vs baseline: 1.0014x; 1.0014x over previous
#include <cuda_runtime.h>
#include <cuda_fp16.h>
#include <math.h>
#include <stdint.h>

#define D_MODEL 1024
#define D_FF    4096
#define NE      8
#define NT      8192
#define ROWS_MAX 17408
#define NTILES  136             // ROWS_MAX/128 m-tiles

// ---------------- static scratch (no runtime allocation allowed) ----------------
__device__ int    g_topk_idx[NT * 2];
__device__ float  g_topk_prob[NT * 2];
__device__ int    g_pos[NT * 2];
__device__ int    g_counts[NE];
__device__ float  g_probs_sum[NE];
__device__ int    g_poff[NE + 1];
__device__ int    g_cursor[NE];
__device__ __half g_xa[(size_t)ROWS_MAX * D_MODEL];       // permuted fp16 A for GEMM1
__device__ __half g_w1t[(size_t)NE * D_FF * D_MODEL];     // w1^T [e][f][k] fp16
__device__ __half g_w2t[(size_t)NE * D_MODEL * D_FF];     // w2^T [e][d][k] fp16
__device__ __half g_h[(size_t)ROWS_MAX * D_FF];           // GEMM1 out fp16
__device__ float  g_y[(size_t)ROWS_MAX * D_MODEL];        // GEMM2 out fp32

// ---------------- PTX helpers (arch-portable only) ----------------
__device__ __forceinline__ uint32_t smem_to_u32(const void* p) {
    uint32_t a;
    asm("{ .reg .u64 t; cvta.to.shared.u64 t, %1; cvt.u32.u64 %0, t; }" : "=r"(a) : "l"(p));
    return a;
}
__device__ __forceinline__ void cp16(uint32_t s, const void* g) {
    asm volatile("cp.async.cg.shared.global [%0], [%1], 16;\n" :: "r"(s), "l"(g) : "memory");
}
#define CP_COMMIT() asm volatile("cp.async.commit_group;\n" ::: "memory")
#define CP_WAIT(n)  asm volatile("cp.async.wait_group %0;\n" :: "n"(n) : "memory")

__device__ __forceinline__ void ldsm_x4(uint32_t& r0, uint32_t& r1, uint32_t& r2,
                                        uint32_t& r3, uint32_t addr) {
    asm volatile("ldmatrix.sync.aligned.m8n8.x4.shared.b16 {%0,%1,%2,%3}, [%4];"
                 : "=r"(r0), "=r"(r1), "=r"(r2), "=r"(r3) : "r"(addr));
}
__device__ __forceinline__ void mma_f16(float* c, const uint32_t* a, const uint32_t* b) {
    asm volatile(
        "mma.sync.aligned.m16n8k16.row.col.f32.f16.f16.f32 "
        "{%0,%1,%2,%3},{%4,%5,%6,%7},{%8,%9},{%0,%1,%2,%3};"
        : "+f"(c[0]), "+f"(c[1]), "+f"(c[2]), "+f"(c[3])
        : "r"(a[0]), "r"(a[1]), "r"(a[2]), "r"(a[3]), "r"(b[0]), "r"(b[1]));
}

// ---------------- init ----------------
__global__ void k_init() {
    int i = threadIdx.x;
    if (i < NE) { g_counts[i] = 0; g_probs_sum[i] = 0.f; g_cursor[i] = 0; }
}

// ---------------- router: 1 warp per token ----------------
__global__ void __launch_bounds__(256) k_router(const float* __restrict__ x,
                                                const float* __restrict__ gw,
                                                const float* __restrict__ gb) {
    __shared__ float gws[NE * D_MODEL];
    __shared__ float psum[NE];
    __shared__ int   scnt[NE];
    int tid = threadIdx.x;
    for (int i = tid; i < NE * D_MODEL; i += 256) {
        int d = i >> 3, e = i & 7;
        gws[e * D_MODEL + d] = gw[i];
    }
    if (tid < NE) { psum[tid] = 0.f; scnt[tid] = 0; }
    __syncthreads();

    int lane = tid & 31, warp = tid >> 5;
    int t = blockIdx.x * 8 + warp;
    const float* xr = x + (size_t)t * D_MODEL;

    float acc[NE];
#pragma unroll
    for (int e = 0; e < NE; e++) acc[e] = 0.f;
    for (int i = 0; i < D_MODEL / 32; i++) {
        int d = i * 32 + lane;
        float xv = xr[d];
#pragma unroll
        for (int e = 0; e < NE; e++) acc[e] += xv * gws[e * D_MODEL + d];
    }
#pragma unroll
    for (int e = 0; e < NE; e++)
        for (int off = 16; off > 0; off >>= 1)
            acc[e] += __shfl_xor_sync(0xffffffffu, acc[e], off);

    if (lane == 0) {
        float l[NE], p[NE];
        float m = -1e30f;
#pragma unroll
        for (int e = 0; e < NE; e++) { l[e] = acc[e] + gb[e]; m = fmaxf(m, l[e]); }
        float s = 0.f;
#pragma unroll
        for (int e = 0; e < NE; e++) { p[e] = expf(l[e] - m); s += p[e]; }
        float inv = 1.f / s;
#pragma unroll
        for (int e = 0; e < NE; e++) { p[e] *= inv; atomicAdd(&psum[e], p[e]); }
        int e1 = 0;
#pragma unroll
        for (int e = 1; e < NE; e++) if (p[e] > p[e1]) e1 = e;
        int e2 = -1;
#pragma unroll
        for (int e = 0; e < NE; e++) {
            if (e == e1) continue;
            if (e2 < 0 || p[e] > p[e2]) e2 = e;
        }
        float pr = 1.f / (p[e1] + p[e2]);
        g_topk_idx[2 * t] = e1;     g_topk_idx[2 * t + 1] = e2;
        g_topk_prob[2 * t] = p[e1] * pr; g_topk_prob[2 * t + 1] = p[e2] * pr;
        atomicAdd(&scnt[e1], 1);
        atomicAdd(&scnt[e2], 1);
    }
    __syncthreads();
    if (tid < NE) {
        atomicAdd(&g_probs_sum[tid], psum[tid]);
        atomicAdd(&g_counts[tid], scnt[tid]);
    }
}

// ---------------- stats + padded segment offsets ----------------
__global__ void k_stats(float* __restrict__ out) {
    if (threadIdx.x == 0) {
        int off = 0;
        for (int e = 0; e < NE; e++) {
            g_poff[e] = off;
            off += ((g_counts[e] + 127) >> 7) << 7;
        }
        g_poff[NE] = off;
        float* tail = out + (size_t)NT * D_MODEL;
        for (int e = 0; e < NE; e++) tail[e] = (float)g_counts[e] / (float)(NT * 2);
        float avg[NE], mean = 0.f;
        for (int e = 0; e < NE; e++) { avg[e] = g_probs_sum[e] / (float)NT; mean += avg[e]; }
        mean /= (float)NE;
        float var = 0.f;
        for (int e = 0; e < NE; e++) { float d = avg[e] - mean; var += d * d; }
        tail[NE] = var / (float)(NE - 1);   // ddof=1
    }
}

// ---------------- scatter slots ----------------
__global__ void k_scatter() {
    int s = blockIdx.x * blockDim.x + threadIdx.x;
    int e = g_topk_idx[s];
    int p = g_poff[e] + atomicAdd(&g_cursor[e], 1);
    g_pos[s] = p;
}

// ---------------- pack: x rows -> permuted fp16 A ----------------
__global__ void __launch_bounds__(256) k_pack(const float* __restrict__ x) {
    int s = blockIdx.x;
    int tok = s >> 1;
    int p = g_pos[s];
    int i = threadIdx.x;
    float4 v = *(const float4*)&x[(size_t)tok * D_MODEL + i * 4];
    __half2 h0 = __floats2half2_rn(v.x, v.y);
    __half2 h1 = __floats2half2_rn(v.z, v.w);
    __half2* dst = (__half2*)&g_xa[(size_t)p * D_MODEL + i * 4];
    dst[0] = h0;
    dst[1] = h1;
}

// ---------------- weight transpose to K-major fp16 ----------------
template <int R, int C>
__global__ void __launch_bounds__(256) k_transpose(const float* __restrict__ src,
                                                   __half* __restrict__ dst) {
    __shared__ float t[32][33];
    int e = blockIdx.z;
    const float* s = src + (size_t)e * R * C;
    __half* d = dst + (size_t)e * R * C;
    int c0 = blockIdx.x * 32, r0 = blockIdx.y * 32;
#pragma unroll
    for (int j = 0; j < 32; j += 8)
        t[threadIdx.y + j][threadIdx.x] =
            s[(size_t)(r0 + threadIdx.y + j) * C + c0 + threadIdx.x];
    __syncthreads();
#pragma unroll
    for (int j = 0; j < 32; j += 8)
        d[(size_t)(c0 + threadIdx.y + j) * R + r0 + threadIdx.x] =
            __float2half_rn(t[threadIdx.x][threadIdx.y + j]);
}

// ---------------- fp16 mma GEMM: block 128m x 128n, warp 64x32, K-chunk 64 ----------
// 3-stage cp.async, SMEM 32KB/stage = 96KB, 2 CTAs/SM, acc = 64 regs/thread
#define ST_A 16384
#define ST_B 16384
#define ST_SZ (ST_A + ST_B)
#define SMEM_GEMM (3 * ST_SZ)   // 98304

__device__ __forceinline__ void fill_stage(uint32_t aS, uint32_t bS,
                                           const __half* __restrict__ Ab,
                                           const __half* __restrict__ Bb,
                                           int koff, int kdim, int tid) {
#pragma unroll
    for (int i = 0; i < 4; i++) {           // A: 128 rows * 8 chunks = 1024 cp16
        int id = tid + i * 256;
        int row = id >> 3, ch = id & 7;
        uint32_t dst = aS + row * 128 + ((uint32_t)(ch ^ (row & 7)) << 4);
        cp16(dst, Ab + (size_t)row * kdim + koff + ch * 8);
    }
#pragma unroll
    for (int i = 0; i < 4; i++) {           // B: 128 rows * 8 chunks = 1024 cp16
        int id = tid + i * 256;
        int row = id >> 3, ch = id & 7;
        uint32_t dst = bS + row * 128 + ((uint32_t)(ch ^ (row & 7)) << 4);
        cp16(dst, Bb + (size_t)row * kdim + koff + ch * 8);
    }
}

template <int KDIM, int NDIM, bool FIRST>
__global__ void __launch_bounds__(256, 2) k_gemm_f16(const __half* __restrict__ Bg,
                                                     const float* __restrict__ bias) {
    extern __shared__ char smem[];
    const int row0 = blockIdx.x * 128;
    if (row0 >= g_poff[NE]) return;
    int e = 0;
#pragma unroll
    for (int i = 1; i < NE; i++) if (row0 >= g_poff[i]) e = i;
    const int n0 = blockIdx.y * 128;
    const int tid = threadIdx.x, lane = tid & 31, wid = tid >> 5;
    const int wm = wid & 1, wn = wid >> 1;          // 2 x 4 warp grid: warp 64m x 32n
    const uint32_t sBase = smem_to_u32(smem);
    const __half* Ab = (FIRST ? g_xa : g_h) + (size_t)row0 * KDIM;
    const __half* Bb = Bg + (size_t)e * KDIM * NDIM + (size_t)n0 * KDIM;
    const int NKT = KDIM / 64;

    // prologue: 2 stages in flight
    fill_stage(sBase, sBase + ST_A, Ab, Bb, 0, KDIM, tid);
    CP_COMMIT();
    fill_stage(sBase + ST_SZ, sBase + ST_SZ + ST_A, Ab, Bb, 64, KDIM, tid);
    CP_COMMIT();

    float acc[4][4][4];
#pragma unroll
    for (int a = 0; a < 4; a++)
#pragma unroll
        for (int b = 0; b < 4; b++)
#pragma unroll
            for (int c = 0; c < 4; c++) acc[a][b][c] = 0.f;

    const int m0w = wm * 64, n0w = wn * 32;
    const int lrA = lane & 15;                        // A row within m16 frag
    const int lqA = lane >> 4;                        // A k-half select
    const int lrB = (lane & 7) + ((lane & 16) >> 1);  // B row within n16 group
    const int lkB = (lane >> 3) & 1;                  // B k-half select
    const int lsw = lane & 7;                         // swizzle row bits

#pragma unroll 1
    for (int kt = 0; kt < NKT; kt++) {
        CP_WAIT(1);
        __syncthreads();
        const int cn = kt + 2;
        if (cn < NKT) {
            const uint32_t s2 = sBase + (uint32_t)(cn % 3) * ST_SZ;
            fill_stage(s2, s2 + ST_A, Ab, Bb, cn * 64, KDIM, tid);
        }
        CP_COMMIT();
        const uint32_t sS = sBase + (uint32_t)(kt % 3) * ST_SZ;
        const uint32_t aS = sS, bS = sS + ST_A;
#pragma unroll
        for (int kk = 0; kk < 4; kk++) {
            const uint32_t swA = (uint32_t)(((kk * 2 + lqA) ^ lsw) << 4);
            const uint32_t swB = (uint32_t)(((kk * 2 + lkB) ^ lsw) << 4);
            uint32_t a[4][4];
#pragma unroll
            for (int mf = 0; mf < 4; mf++) {
                uint32_t addr = aS + (uint32_t)(m0w + mf * 16 + lrA) * 128 + swA;
                ldsm_x4(a[mf][0], a[mf][1], a[mf][2], a[mf][3], addr);
            }
#pragma unroll
            for (int nf = 0; nf < 2; nf++) {
                uint32_t b[4];
                uint32_t addr = bS + (uint32_t)(n0w + nf * 16 + lrB) * 128 + swB;
                ldsm_x4(b[0], b[1], b[2], b[3], addr);
#pragma unroll
                for (int mf = 0; mf < 4; mf++) {
                    mma_f16(acc[mf][nf * 2],     a[mf], b);
                    mma_f16(acc[mf][nf * 2 + 1], a[mf], b + 2);
                }
            }
        }
    }

    // epilogue
    const int gid = lane >> 2, ktid = lane & 3;
#pragma unroll
    for (int mf = 0; mf < 4; mf++) {
        const int r0 = row0 + m0w + mf * 16 + gid;
        const int r1 = r0 + 8;
#pragma unroll
        for (int nf8 = 0; nf8 < 4; nf8++) {
            const int col = n0 + n0w + nf8 * 8 + ktid * 2;
            float* c = acc[mf][nf8];
            if (FIRST) {
                float b0v = bias[e * NDIM + col];
                float b1v = bias[e * NDIM + col + 1];
                __half2 h0 = __floats2half2_rn(fmaxf(c[0] + b0v, 0.f), fmaxf(c[1] + b1v, 0.f));
                __half2 h1 = __floats2half2_rn(fmaxf(c[2] + b0v, 0.f), fmaxf(c[3] + b1v, 0.f));
                *(__half2*)&g_h[(size_t)r0 * NDIM + col] = h0;
                *(__half2*)&g_h[(size_t)r1 * NDIM + col] = h1;
            } else {
                *(float2*)&g_y[(size_t)r0 * NDIM + col] = make_float2(c[0], c[1]);
                *(float2*)&g_y[(size_t)r1 * NDIM + col] = make_float2(c[2], c[3]);
            }
        }
    }
}

// ---------------- combine ----------------
__global__ void __launch_bounds__(256) k_combine(const float* __restrict__ b2,
                                                 float* __restrict__ out) {
    int t = blockIdx.x, i = threadIdx.x;
    int e0 = g_topk_idx[2 * t], e1 = g_topk_idx[2 * t + 1];
    float p0 = g_topk_prob[2 * t], p1 = g_topk_prob[2 * t + 1];
    int q0 = g_pos[2 * t], q1 = g_pos[2 * t + 1];
    float4 y0 = *(const float4*)&g_y[(size_t)q0 * D_MODEL + i * 4];
    float4 y1 = *(const float4*)&g_y[(size_t)q1 * D_MODEL + i * 4];
    float4 c0 = *(const float4*)&b2[(size_t)e0 * D_MODEL + i * 4];
    float4 c1 = *(const float4*)&b2[(size_t)e1 * D_MODEL + i * 4];
    float4 o;
    o.x = p0 * (y0.x + c0.x) + p1 * (y1.x + c1.x);
    o.y = p0 * (y0.y + c0.y) + p1 * (y1.y + c1.y);
    o.z = p0 * (y0.z + c0.z) + p1 * (y1.z + c1.z);
    o.w = p0 * (y0.w + c0.w) + p1 * (y1.w + c1.w);
    *(float4*)&out[(size_t)t * D_MODEL + i * 4] = o;
}

// ---------------- launch ----------------
extern "C" void kernel_launch(void* const* d_in, const int* in_sizes, int n_in,
                              void* d_out, int out_size) {
    (void)in_sizes; (void)n_in; (void)out_size;
    const float* x  = (const float*)d_in[0];
    const float* gw = (const float*)d_in[1];
    const float* gb = (const float*)d_in[2];
    const float* w1 = (const float*)d_in[3];
    const float* b1 = (const float*)d_in[4];
    const float* w2 = (const float*)d_in[5];
    const float* b2 = (const float*)d_in[6];
    float* out = (float*)d_out;

    static int attr_done = 0;
    if (!attr_done) {
        cudaFuncSetAttribute(k_gemm_f16<D_MODEL, D_FF, true>,
                             cudaFuncAttributeMaxDynamicSharedMemorySize, SMEM_GEMM);
        cudaFuncSetAttribute(k_gemm_f16<D_FF, D_MODEL, false>,
                             cudaFuncAttributeMaxDynamicSharedMemorySize, SMEM_GEMM);
        attr_done = 1;
    }

    k_init<<<1, 32>>>();
    k_router<<<NT / 8, 256>>>(x, gw, gb);
    k_stats<<<1, 32>>>(out);
    k_scatter<<<(NT * 2) / 256, 256>>>();
    k_pack<<<NT * 2, 256>>>(x);
    k_transpose<D_MODEL, D_FF><<<dim3(D_FF / 32, D_MODEL / 32, NE), dim3(32, 8)>>>(w1, g_w1t);
    k_transpose<D_FF, D_MODEL><<<dim3(D_MODEL / 32, D_FF / 32, NE), dim3(32, 8)>>>(w2, g_w2t);
    k_gemm_f16<D_MODEL, D_FF, true ><<<dim3(NTILES, D_FF / 128), 256, SMEM_GEMM>>>(g_w1t, b1);
    k_gemm_f16<D_FF, D_MODEL, false><<<dim3(NTILES, D_MODEL / 128), 256, SMEM_GEMM>>>(g_w2t, (const float*)0);
    k_combine<<<NT, 256>>>(b2, out);
}

// round 8
// speedup vs baseline: 6.2028x; 6.1942x over previous
#include <cuda_runtime.h>
#include <math.h>
#include <stdint.h>

#define D_MODEL 1024
#define D_FF    4096
#define NE      8
#define NT      8192
#define ROWS_MAX 17408
#define NTILES  136             // ROWS_MAX/128 m-tiles

// ---------------- static scratch (no runtime allocation allowed) ----------------
__device__ int   g_topk_idx[NT * 2];
__device__ float g_topk_prob[NT * 2];
__device__ int   g_pos[NT * 2];
__device__ int   g_counts[NE];
__device__ float g_probs_sum[NE];
__device__ int   g_poff[NE + 1];
__device__ int   g_cursor[NE];
__device__ float g_xa[(size_t)ROWS_MAX * D_MODEL];        // permuted + tf32-rounded x
__device__ float g_w1r[(size_t)NE * D_MODEL * D_FF];      // tf32-rounded w1 [e][k][n]
__device__ float g_w2r[(size_t)NE * D_FF * D_MODEL];      // tf32-rounded w2 [e][k][n]
__device__ float g_h[(size_t)ROWS_MAX * D_FF];            // GEMM1 out, tf32-rounded fp32
__device__ float g_y[(size_t)ROWS_MAX * D_MODEL];         // GEMM2 out fp32

// ---------------- PTX helpers (arch-portable only) ----------------
__device__ __forceinline__ uint32_t smem_to_u32(const void* p) {
    uint32_t a;
    asm("{ .reg .u64 t; cvta.to.shared.u64 t, %1; cvt.u32.u64 %0, t; }" : "=r"(a) : "l"(p));
    return a;
}
__device__ __forceinline__ void cp16(uint32_t s, const void* g) {
    asm volatile("cp.async.cg.shared.global [%0], [%1], 16;\n" :: "r"(s), "l"(g) : "memory");
}
#define CP_COMMIT() asm volatile("cp.async.commit_group;\n" ::: "memory")
#define CP_WAIT(n)  asm volatile("cp.async.wait_group %0;\n" :: "n"(n) : "memory")

__device__ __forceinline__ void mma_tf32(float* c, const unsigned* a, const unsigned* b) {
    asm volatile(
        "mma.sync.aligned.m16n8k8.row.col.f32.tf32.tf32.f32 "
        "{%0,%1,%2,%3}, {%4,%5,%6,%7}, {%8,%9}, {%0,%1,%2,%3};\n"
        : "+f"(c[0]), "+f"(c[1]), "+f"(c[2]), "+f"(c[3])
        : "r"(a[0]), "r"(a[1]), "r"(a[2]), "r"(a[3]), "r"(b[0]), "r"(b[1]));
}
__device__ __forceinline__ float rna_tf32(float v) {
    float r;
    asm("cvt.rna.tf32.f32 %0, %1;\n" : "=f"(r) : "f"(v));
    return r;
}
__device__ __forceinline__ float4 rna_tf32_4(float4 v) {
    v.x = rna_tf32(v.x); v.y = rna_tf32(v.y);
    v.z = rna_tf32(v.z); v.w = rna_tf32(v.w);
    return v;
}

// ---------------- init ----------------
__global__ void k_init() {
    int i = threadIdx.x;
    if (i < NE) { g_counts[i] = 0; g_probs_sum[i] = 0.f; g_cursor[i] = 0; }
}

// ---------------- round weights to tf32 (prepass, pure bandwidth) ----------------
__global__ void __launch_bounds__(256) k_round(const float* __restrict__ in,
                                               float* __restrict__ out, int n4) {
    int i = blockIdx.x * blockDim.x + threadIdx.x;
    int stride = gridDim.x * blockDim.x;
    for (; i < n4; i += stride) {
        float4 v = *(const float4*)(in + (size_t)i * 4);
        *(float4*)(out + (size_t)i * 4) = rna_tf32_4(v);
    }
}

// ---------------- router: 1 warp per token ----------------
__global__ void __launch_bounds__(256) k_router(const float* __restrict__ x,
                                                const float* __restrict__ gw,
                                                const float* __restrict__ gb) {
    __shared__ float gws[NE * D_MODEL];
    __shared__ float psum[NE];
    __shared__ int   scnt[NE];
    int tid = threadIdx.x;
    for (int i = tid; i < NE * D_MODEL; i += 256) {
        int d = i >> 3, e = i & 7;
        gws[e * D_MODEL + d] = gw[i];
    }
    if (tid < NE) { psum[tid] = 0.f; scnt[tid] = 0; }
    __syncthreads();

    int lane = tid & 31, warp = tid >> 5;
    int t = blockIdx.x * 8 + warp;
    const float* xr = x + (size_t)t * D_MODEL;

    float acc[NE];
#pragma unroll
    for (int e = 0; e < NE; e++) acc[e] = 0.f;
    for (int i = 0; i < D_MODEL / 32; i++) {
        int d = i * 32 + lane;
        float xv = xr[d];
#pragma unroll
        for (int e = 0; e < NE; e++) acc[e] += xv * gws[e * D_MODEL + d];
    }
#pragma unroll
    for (int e = 0; e < NE; e++)
        for (int off = 16; off > 0; off >>= 1)
            acc[e] += __shfl_xor_sync(0xffffffffu, acc[e], off);

    if (lane == 0) {
        float l[NE], p[NE];
        float m = -1e30f;
#pragma unroll
        for (int e = 0; e < NE; e++) { l[e] = acc[e] + gb[e]; m = fmaxf(m, l[e]); }
        float s = 0.f;
#pragma unroll
        for (int e = 0; e < NE; e++) { p[e] = expf(l[e] - m); s += p[e]; }
        float inv = 1.f / s;
#pragma unroll
        for (int e = 0; e < NE; e++) { p[e] *= inv; atomicAdd(&psum[e], p[e]); }
        int e1 = 0;
#pragma unroll
        for (int e = 1; e < NE; e++) if (p[e] > p[e1]) e1 = e;
        int e2 = -1;
#pragma unroll
        for (int e = 0; e < NE; e++) {
            if (e == e1) continue;
            if (e2 < 0 || p[e] > p[e2]) e2 = e;
        }
        float pr = 1.f / (p[e1] + p[e2]);
        g_topk_idx[2 * t] = e1;     g_topk_idx[2 * t + 1] = e2;
        g_topk_prob[2 * t] = p[e1] * pr; g_topk_prob[2 * t + 1] = p[e2] * pr;
        atomicAdd(&scnt[e1], 1);
        atomicAdd(&scnt[e2], 1);
    }
    __syncthreads();
    if (tid < NE) {
        atomicAdd(&g_probs_sum[tid], psum[tid]);
        atomicAdd(&g_counts[tid], scnt[tid]);
    }
}

// ---------------- stats + padded segment offsets ----------------
__global__ void k_stats(float* __restrict__ out) {
    if (threadIdx.x == 0) {
        int off = 0;
        for (int e = 0; e < NE; e++) {
            g_poff[e] = off;
            off += ((g_counts[e] + 127) >> 7) << 7;
        }
        g_poff[NE] = off;
        float* tail = out + (size_t)NT * D_MODEL;
        for (int e = 0; e < NE; e++) tail[e] = (float)g_counts[e] / (float)(NT * 2);
        float avg[NE], mean = 0.f;
        for (int e = 0; e < NE; e++) { avg[e] = g_probs_sum[e] / (float)NT; mean += avg[e]; }
        mean /= (float)NE;
        float var = 0.f;
        for (int e = 0; e < NE; e++) { float d = avg[e] - mean; var += d * d; }
        tail[NE] = var / (float)(NE - 1);   // ddof=1
    }
}

// ---------------- scatter slots ----------------
__global__ void k_scatter() {
    int s = blockIdx.x * blockDim.x + threadIdx.x;
    int e = g_topk_idx[s];
    int p = g_poff[e] + atomicAdd(&g_cursor[e], 1);
    g_pos[s] = p;
}

// ---------------- pack: gather x rows into permuted order, tf32-rounded --------
// also zero-fills padding rows so GEMM A reads are never garbage
__global__ void __launch_bounds__(256) k_pack(const float* __restrict__ x) {
    int s = blockIdx.x;
    int i = threadIdx.x;
    if (s >= NT * 2) {   // padding-clear blocks: zero rows at the tail of each segment
        return;
    }
    int tok = s >> 1;
    int p = g_pos[s];
    float4 v = *(const float4*)&x[(size_t)tok * D_MODEL + i * 4];
    *(float4*)&g_xa[(size_t)p * D_MODEL + i * 4] = rna_tf32_4(v);
}

// ---------------- tf32 GEMM: 128x128 block, 16-k stages, 3-stage cp.async ------
// SMEM per stage: A 128x16 @stride20 = 10240B, B 16x128 @stride136 = 8704B
#define A_ST 2560   // floats per A stage
#define B_ST 2176   // floats per B stage
#define SMEM_GEMM ((3 * (A_ST + B_ST)) * 4)   // 56832 bytes

__device__ __forceinline__ void fill_stage(uint32_t aS, uint32_t bS,
                                           const float* __restrict__ A0,
                                           const float* __restrict__ B0,
                                           int koff, int kdim, int ndim, int tid) {
#pragma unroll
    for (int i = 0; i < 2; i++) {               // A: 512 cp16 (128 rows x 4 chunks)
        int id = tid + i * 256;
        int row = id >> 2, q = id & 3;
        cp16(aS + (uint32_t)(row * 20 + q * 4) * 4,
             A0 + (size_t)row * kdim + koff + q * 4);
    }
#pragma unroll
    for (int i = 0; i < 2; i++) {               // B: 512 cp16 (16 k-rows x 32 chunks)
        int id = tid + i * 256;
        int k = id >> 5, ch = id & 31;
        cp16(bS + (uint32_t)(k * 136 + ch * 4) * 4,
             B0 + (size_t)(koff + k) * ndim + ch * 4);
    }
}

template <int KDIM, int NDIM, bool FIRST>
__global__ void __launch_bounds__(256, 2) k_gemm(const float* __restrict__ Bg,
                                                 const float* __restrict__ bias) {
    extern __shared__ float sm[];
    const int row0 = blockIdx.x * 128;
    if (row0 >= g_poff[NE]) return;
    int e = 0;
#pragma unroll
    for (int i = 1; i < NE; i++) if (row0 >= g_poff[i]) e = i;
    const int n0 = blockIdx.y * 128;
    const int tid = threadIdx.x, lane = tid & 31, warp = tid >> 5;
    const int wm = warp & 1, wn = warp >> 1;
    const int gid = lane >> 2, ktid = lane & 3;
    const uint32_t sb = smem_to_u32(sm);
    const uint32_t aU = sb, bU = sb + 3 * A_ST * 4;

    // IMPORTANT: resolve device symbols IN DEVICE CODE (host symbol decay = garbage ptr)
    const float* A0 = (FIRST ? g_xa : g_h) + (size_t)row0 * KDIM;
    const float* B0 = Bg + (size_t)e * KDIM * NDIM + n0;
    const int NKT = KDIM / 16;

    // prologue: 2 stages in flight
    fill_stage(aU, bU, A0, B0, 0, KDIM, NDIM, tid);
    CP_COMMIT();
    fill_stage(aU + A_ST * 4, bU + B_ST * 4, A0, B0, 16, KDIM, NDIM, tid);
    CP_COMMIT();

    float acc[4][4][4];
#pragma unroll
    for (int a = 0; a < 4; a++)
#pragma unroll
        for (int b = 0; b < 4; b++)
#pragma unroll
            for (int c = 0; c < 4; c++) acc[a][b][c] = 0.f;

#pragma unroll 1
    for (int kt = 0; kt < NKT; kt++) {
        CP_WAIT(1);
        __syncthreads();
        const int cn = kt + 2;
        if (cn < NKT) {
            const int s2 = cn % 3;
            fill_stage(aU + s2 * A_ST * 4, bU + s2 * B_ST * 4,
                       A0, B0, cn * 16, KDIM, NDIM, tid);
        }
        CP_COMMIT();
        const float* Asb = sm + (kt % 3) * A_ST;
        const float* Bsb = sm + 3 * A_ST + (kt % 3) * B_ST;
#pragma unroll
        for (int kk = 0; kk < 16; kk += 8) {
            unsigned a[4][4], b[4][2];
#pragma unroll
            for (int mt = 0; mt < 4; mt++) {
                int rb_ = wm * 64 + mt * 16;
                a[mt][0] = __float_as_uint(Asb[(rb_ + gid) * 20 + kk + ktid]);
                a[mt][1] = __float_as_uint(Asb[(rb_ + gid + 8) * 20 + kk + ktid]);
                a[mt][2] = __float_as_uint(Asb[(rb_ + gid) * 20 + kk + ktid + 4]);
                a[mt][3] = __float_as_uint(Asb[(rb_ + gid + 8) * 20 + kk + ktid + 4]);
            }
#pragma unroll
            for (int nt = 0; nt < 4; nt++) {
                int col = wn * 32 + nt * 8 + gid;
                b[nt][0] = __float_as_uint(Bsb[(kk + ktid) * 136 + col]);
                b[nt][1] = __float_as_uint(Bsb[(kk + ktid + 4) * 136 + col]);
            }
#pragma unroll
            for (int mt = 0; mt < 4; mt++)
#pragma unroll
                for (int nt = 0; nt < 4; nt++) mma_tf32(acc[mt][nt], a[mt], b[nt]);
        }
    }

    // epilogue
#pragma unroll
    for (int mt = 0; mt < 4; mt++) {
        int rr0 = row0 + wm * 64 + mt * 16 + gid;
        int rr1 = rr0 + 8;
#pragma unroll
        for (int nt = 0; nt < 4; nt++) {
            int c = n0 + wn * 32 + nt * 8 + ktid * 2;
            float* a = acc[mt][nt];
            if (FIRST) {
                float bb0 = bias[e * NDIM + c];
                float bb1 = bias[e * NDIM + c + 1];
                float2 v0, v1;
                v0.x = rna_tf32(fmaxf(a[0] + bb0, 0.f));
                v0.y = rna_tf32(fmaxf(a[1] + bb1, 0.f));
                v1.x = rna_tf32(fmaxf(a[2] + bb0, 0.f));
                v1.y = rna_tf32(fmaxf(a[3] + bb1, 0.f));
                *(float2*)&g_h[(size_t)rr0 * D_FF + c] = v0;
                *(float2*)&g_h[(size_t)rr1 * D_FF + c] = v1;
            } else {
                *(float2*)&g_y[(size_t)rr0 * D_MODEL + c] = make_float2(a[0], a[1]);
                *(float2*)&g_y[(size_t)rr1 * D_MODEL + c] = make_float2(a[2], a[3]);
            }
        }
    }
}

// ---------------- combine ----------------
__global__ void __launch_bounds__(256) k_combine(const float* __restrict__ b2,
                                                 float* __restrict__ out) {
    int t = blockIdx.x, i = threadIdx.x;
    int e0 = g_topk_idx[2 * t], e1 = g_topk_idx[2 * t + 1];
    float p0 = g_topk_prob[2 * t], p1 = g_topk_prob[2 * t + 1];
    int q0 = g_pos[2 * t], q1 = g_pos[2 * t + 1];
    float4 y0 = *(const float4*)&g_y[(size_t)q0 * D_MODEL + i * 4];
    float4 y1 = *(const float4*)&g_y[(size_t)q1 * D_MODEL + i * 4];
    float4 c0 = *(const float4*)&b2[(size_t)e0 * D_MODEL + i * 4];
    float4 c1 = *(const float4*)&b2[(size_t)e1 * D_MODEL + i * 4];
    float4 o;
    o.x = p0 * (y0.x + c0.x) + p1 * (y1.x + c1.x);
    o.y = p0 * (y0.y + c0.y) + p1 * (y1.y + c1.y);
    o.z = p0 * (y0.z + c0.z) + p1 * (y1.z + c1.z);
    o.w = p0 * (y0.w + c0.w) + p1 * (y1.w + c1.w);
    *(float4*)&out[(size_t)t * D_MODEL + i * 4] = o;
}

// ---------------- launch ----------------
extern "C" void kernel_launch(void* const* d_in, const int* in_sizes, int n_in,
                              void* d_out, int out_size) {
    (void)in_sizes; (void)n_in; (void)out_size;
    const float* x  = (const float*)d_in[0];
    const float* gw = (const float*)d_in[1];
    const float* gb = (const float*)d_in[2];
    const float* w1 = (const float*)d_in[3];
    const float* b1 = (const float*)d_in[4];
    const float* w2 = (const float*)d_in[5];
    const float* b2 = (const float*)d_in[6];
    float* out = (float*)d_out;

    static int attr_done = 0;
    if (!attr_done) {
        cudaFuncSetAttribute(k_gemm<D_MODEL, D_FF, true>,
                             cudaFuncAttributeMaxDynamicSharedMemorySize, SMEM_GEMM);
        cudaFuncSetAttribute(k_gemm<D_FF, D_MODEL, false>,
                             cudaFuncAttributeMaxDynamicSharedMemorySize, SMEM_GEMM);
        attr_done = 1;
    }

    float* w1r; cudaGetSymbolAddress((void**)&w1r, g_w1r);
    float* w2r; cudaGetSymbolAddress((void**)&w2r, g_w2r);

    k_init<<<1, 32>>>();
    k_router<<<NT / 8, 256>>>(x, gw, gb);
    k_stats<<<1, 32>>>(out);
    k_scatter<<<(NT * 2) / 256, 256>>>();
    k_pack<<<NT * 2, 256>>>(x);
    k_round<<<2048, 256>>>(w1, w1r, NE * D_MODEL * D_FF / 4);
    k_round<<<2048, 256>>>(w2, w2r, NE * D_MODEL * D_FF / 4);
    k_gemm<D_MODEL, D_FF, true ><<<dim3(NTILES, D_FF / 128), 256, SMEM_GEMM>>>(w1r, b1);
    k_gemm<D_FF, D_MODEL, false><<<dim3(NTILES, D_MODEL / 128), 256, SMEM_GEMM>>>(w2r, (const float*)0);
    k_combine<<<NT, 256>>>(b2, out);
}